// round 5
// baseline (speedup 1.0000x reference)
#include <cuda_runtime.h>

// Warp-specialized pipeline, 384 threads/CTA, 2 CTAs/SM (24 warps/SM).
//   tid 0-255   (G, 8 warps): P1 (fc1) + P3 (fc2) GEMMs, f32x2 packed FMA.
//   tid 256-351 (S, 3 warps): 96 sequential material chains (P2), pipelined loads.
//   tid 352-383 (1 warp):     stages x tiles global->shared.
// TT=32 timestep tiles, double-buffered: P2(k) overlaps P3(k-1)+P1(k+1).

typedef unsigned long long u64;

#define NTHREADS 384
#define TT 32
#define NTILES 32
#define BPAD 264   // ==8 (mod 32): P3 y-loads (t3,q8) conflict-free
#define WPAD 20    // SW2 row stride: 20*q8 mod 32 distinct -> weight loads conflict-free
#define XPAD 36    // duplicated x row stride, 16B aligned

__device__ __forceinline__ u64 ffma2(u64 a, u64 b, u64 c) {
    u64 d; asm("fma.rn.f32x2 %0, %1, %2, %3;" : "=l"(d) : "l"(a), "l"(b), "l"(c)); return d;
}
__device__ __forceinline__ u64 addf2(u64 a, u64 b) {
    u64 d; asm("add.rn.f32x2 %0, %1, %2;" : "=l"(d) : "l"(a), "l"(b)); return d;
}
__device__ __forceinline__ u64 pack2(float a, float b) {
    u64 r; asm("mov.b64 %0, {%1, %2};" : "=l"(r) : "f"(a), "f"(b)); return r;
}
__device__ __forceinline__ u64 dup2(float a) {
    u64 r; asm("mov.b64 %0, {%1, %1};" : "=l"(r) : "f"(a)); return r;
}
__device__ __forceinline__ float2 unpack2(u64 v) {
    float2 r; asm("mov.b64 {%0, %1}, %2;" : "=f"(r.x), "=f"(r.y) : "l"(v)); return r;
}

__global__ void __launch_bounds__(NTHREADS, 2)
fused_fea_kernel(const float* __restrict__ x, const float* __restrict__ W1,
                 const float* __restrict__ W2, float* __restrict__ out)
{
    extern __shared__ float sm[];
    float* SW2s = sm;                          // 256*WPAD floats
    float* xsd  = sm + 256 * WPAD;             // 2 * TT*XPAD floats (duplicated x)
    float* buf  = xsd + 2 * TT * XPAD;         // 2 * TT*BPAD floats (+BPAD slack)

    const int tid = threadIdx.x;
    const int b   = blockIdx.x;
    const bool isG = (tid < 256);

    const float* xb = x   + (size_t)b * (1024 * 16);
    float*       ob = out + (size_t)b * (1024 * 16);

    // ---- Prologue ----
    for (int i = tid; i < 4096; i += NTHREADS) {
        int o = i >> 8, l = i & 255;
        SW2s[l * WPAD + o] = log1pf(expf(W2[i]));
    }
    if (tid >= 352) {
        const int j = tid - 352;                  // one timestep each
#pragma unroll
        for (int tile = 0; tile < 2; ++tile) {
            const float4* src = (const float4*)(xb + tile * (TT * 16) + j * 16);
            float* dst = xsd + tile * (TT * XPAD) + j * XPAD;
#pragma unroll
            for (int m = 0; m < 4; ++m) {
                float4 v = src[m];
                ((float4*)dst)[2 * m]     = make_float4(v.x, v.x, v.y, v.y);
                ((float4*)dst)[2 * m + 1] = make_float4(v.z, v.z, v.w, v.w);
            }
        }
    }

    // G: one packed channel pair (lq, lq+128) per thread; tq owns 16 timesteps.
    const int lq = tid & 127;
    const int tq = (tid >> 7) & 1;
    u64 wA[16];
    if (isG) {
        const float4* rA0 = (const float4*)(W1 + lq * 16);
        const float4* rA1 = (const float4*)(W1 + (lq + 128) * 16);
#pragma unroll
        for (int k = 0; k < 4; ++k) {
            float4 a0 = rA0[k], a1 = rA1[k];
            wA[4*k+0] = pack2(a0.x, a1.x); wA[4*k+1] = pack2(a0.y, a1.y);
            wA[4*k+2] = pack2(a0.z, a1.z); wA[4*k+3] = pack2(a0.w, a1.w);
        }
    }

    // Material constants.
    const float NUv    = 0.3f;
    const float CEL00  = 200.0f / 0.91f;
    const float CEL01  = CEL00 * 0.3f;
    const float CEL22  = CEL00 * 0.35f;
    const float INV_E  = 1.0f / 200.0f;
    const float INV_G  = 2.6f / 200.0f;
    const float GMOD   = 200.0f / 2.6f;
    const float SY0    = 2.0f, HARD = 10.0f;
    const float INV3GH = 1.0f / (3.0f * GMOD + HARD);
    const float KPEN   = 50.0f;
    const float D0     = 0.1f, INV_DFm = 1.0f / 0.9f;

    float ep1 = 0.f, ep2 = 0.f, ep12 = 0.f, epbar = 0.f, hist = 0.f;
    const int s = tid - 256;         // scan-point index (0..95) for S warps

    const int t3 = tid >> 3;         // P3 timestep (0..31)
    const int q8 = tid & 7;          // P3 l-class: l = 8i + q8

    __syncthreads();

    // ---- Fill: P1(0) ----
    if (isG) {
        float* bufb = buf;
        const float* xsb = xsd;
#pragma unroll
        for (int tp = 0; tp < 8; ++tp) {
            const int t = tq * 16 + 2 * tp;
            const ulonglong2* x0 = (const ulonglong2*)(xsb + t * XPAD);
            const ulonglong2* x1 = (const ulonglong2*)(xsb + (t + 1) * XPAD);
            u64 a0a = 0, a0b = 0, a1a = 0, a1b = 0;
#pragma unroll
            for (int f4 = 0; f4 < 8; ++f4) {
                ulonglong2 u = x0[f4], v = x1[f4];
                a0a = ffma2(wA[2*f4],   u.x, a0a);
                a0b = ffma2(wA[2*f4+1], u.y, a0b);
                a1a = ffma2(wA[2*f4],   v.x, a1a);
                a1b = ffma2(wA[2*f4+1], v.y, a1b);
            }
            float2 h0 = unpack2(addf2(a0a, a0b));
            float2 h1 = unpack2(addf2(a1a, a1b));
            float* r0 = bufb + t * BPAD + lq;
            float* r1 = r0 + BPAD;
            r0[0] = h0.x; r0[128] = h0.y;
            r1[0] = h1.x; r1[128] = h1.y;
        }
    }
    __syncthreads();

    // ---- Pipelined slots ----
    for (int k = 0; k < NTILES; ++k) {
        if (isG) {
            // P3(k-1)
            if (k >= 1) {
                const float* bufb = buf + ((k - 1) & 1) * (TT * BPAD);
                u64 acc[8] = {0,0,0,0,0,0,0,0};
                const float* yrow = bufb + t3 * BPAD + q8;
#pragma unroll 4
                for (int i = 0; i < 32; ++i) {
                    u64 yd = dup2(yrow[8 * i]);
                    const ulonglong2* wp = (const ulonglong2*)(SW2s + (8 * i + q8) * WPAD);
                    ulonglong2 wa = wp[0], wb = wp[1];
                    acc[0] = ffma2(wa.x, yd, acc[0]);
                    acc[1] = ffma2(wa.y, yd, acc[1]);
                    acc[2] = ffma2(wb.x, yd, acc[2]);
                    acc[3] = ffma2(wb.y, yd, acc[3]);
                    ulonglong2 wc = wp[2], wd = wp[3];
                    acc[4] = ffma2(wc.x, yd, acc[4]);
                    acc[5] = ffma2(wc.y, yd, acc[5]);
                    acc[6] = ffma2(wd.x, yd, acc[6]);
                    acc[7] = ffma2(wd.y, yd, acc[7]);
                }
#pragma unroll
                for (int m = 0; m < 8; ++m) {
                    acc[m] = addf2(acc[m], __shfl_xor_sync(0xffffffffu, acc[m], 1));
                    acc[m] = addf2(acc[m], __shfl_xor_sync(0xffffffffu, acc[m], 2));
                    acc[m] = addf2(acc[m], __shfl_xor_sync(0xffffffffu, acc[m], 4));
                }
                if (q8 == 0) {
                    float2* og = (float2*)(ob + (size_t)((k - 1) * TT + t3) * 16);
#pragma unroll
                    for (int m = 0; m < 8; ++m) og[m] = unpack2(acc[m]);
                }
            }
            // G-only barrier: P3 reads complete before P1(k+1) overwrites that buffer.
            asm volatile("bar.sync 1, 256;" ::: "memory");
            // P1(k+1)
            if (k + 1 < NTILES) {
                float* bufb = buf + ((k + 1) & 1) * (TT * BPAD);
                const float* xsb = xsd + ((k + 1) & 1) * (TT * XPAD);
#pragma unroll
                for (int tp = 0; tp < 8; ++tp) {
                    const int t = tq * 16 + 2 * tp;
                    const ulonglong2* x0 = (const ulonglong2*)(xsb + t * XPAD);
                    const ulonglong2* x1 = (const ulonglong2*)(xsb + (t + 1) * XPAD);
                    u64 a0a = 0, a0b = 0, a1a = 0, a1b = 0;
#pragma unroll
                    for (int f4 = 0; f4 < 8; ++f4) {
                        ulonglong2 u = x0[f4], v = x1[f4];
                        a0a = ffma2(wA[2*f4],   u.x, a0a);
                        a0b = ffma2(wA[2*f4+1], u.y, a0b);
                        a1a = ffma2(wA[2*f4],   v.x, a1a);
                        a1b = ffma2(wA[2*f4+1], v.y, a1b);
                    }
                    float2 h0 = unpack2(addf2(a0a, a0b));
                    float2 h1 = unpack2(addf2(a1a, a1b));
                    float* r0 = bufb + t * BPAD + lq;
                    float* r1 = r0 + BPAD;
                    r0[0] = h0.x; r0[128] = h0.y;
                    r1[0] = h1.x; r1[128] = h1.y;
                }
            }
        } else if (s < 64) {
            // P2 bulk: J2 radial return, branchless, next-step loads prefetched.
            float* p = buf + (k & 1) * (TT * BPAD) + s * 3;
            float e1 = p[0], e2 = p[1], e12 = p[2];
            for (int t = 0; t < TT; ++t) {
                float n1 = p[BPAD], n2 = p[BPAD + 1], n12 = p[BPAD + 2]; // prefetch
                float d1 = e1 - ep1, d2 = e2 - ep2, d12 = e12 - ep12;
                float s1  = CEL00 * d1 + CEL01 * d2;
                float s2  = CEL01 * d1 + CEL00 * d2;
                float s12 = CEL22 * d12;
                float qv  = fmaxf(s1 * s1 - s1 * s2 + s2 * s2 + 3.0f * s12 * s12, 1e-12f);
                float rs  = rsqrtf(qv);
                float seq = qv * rs;
                float fy  = seq - (SY0 + HARD * epbar);
                bool  pl  = fy > 0.0f;
                epbar += fmaxf(fy, 0.0f) * INV3GH;
                float r = pl ? (SY0 + HARD * epbar) * rs : 1.0f;
                s1 *= r; s2 *= r; s12 *= r;
                ep1  = pl ? e1  - (s1 - NUv * s2) * INV_E : ep1;
                ep2  = pl ? e2  - (s2 - NUv * s1) * INV_E : ep2;
                ep12 = pl ? e12 - s12 * INV_G             : ep12;
                p[0] = s1; p[1] = s2; p[2] = s12;
                p += BPAD; e1 = n1; e2 = n2; e12 = n12;
            }
        } else if (s < 96) {
            // P2 cohesive: bilinear damage, prefetched.
            float* p = buf + (k & 1) * (TT * BPAD) + 192 + (s - 64) * 2;
            float dn = p[0], ds = p[1];
            for (int t = 0; t < TT; ++t) {
                float mn = p[BPAD], ms = p[BPAD + 1];   // prefetch
                float dnp = fmaxf(dn, 0.0f);
                float q2  = fmaxf(dnp * dnp + ds * ds, 1e-12f);
                float lam = q2 * rsqrtf(q2);
                hist = fmaxf(hist, lam);
                float dmg = __fdividef(hist - D0, hist) * INV_DFm;
                dmg = fminf(fmaxf(dmg, 0.0f), 1.0f);
                float omd = 1.0f - dmg;
                p[0] = KPEN * dn * (dn > 0.0f ? omd : 1.0f);
                p[1] = omd * KPEN * ds;
                p += BPAD; dn = mn; ds = ms;
            }
        } else {
            // Stager warp: x tile (k+2) into xsd[k&1].
            if (k + 2 < NTILES) {
                const int j = tid - 352;
                const float4* src = (const float4*)(xb + (k + 2) * (TT * 16) + j * 16);
                float* dst = xsd + (k & 1) * (TT * XPAD) + j * XPAD;
#pragma unroll
                for (int m = 0; m < 4; ++m) {
                    float4 v = src[m];
                    ((float4*)dst)[2 * m]     = make_float4(v.x, v.x, v.y, v.y);
                    ((float4*)dst)[2 * m + 1] = make_float4(v.z, v.z, v.w, v.w);
                }
            }
        }
        __syncthreads();
    }

    // ---- Drain: P3(31) ----
    if (isG) {
        const float* bufb = buf + ((NTILES - 1) & 1) * (TT * BPAD);
        u64 acc[8] = {0,0,0,0,0,0,0,0};
        const float* yrow = bufb + t3 * BPAD + q8;
#pragma unroll 4
        for (int i = 0; i < 32; ++i) {
            u64 yd = dup2(yrow[8 * i]);
            const ulonglong2* wp = (const ulonglong2*)(SW2s + (8 * i + q8) * WPAD);
            ulonglong2 wa = wp[0], wb = wp[1];
            acc[0] = ffma2(wa.x, yd, acc[0]);
            acc[1] = ffma2(wa.y, yd, acc[1]);
            acc[2] = ffma2(wb.x, yd, acc[2]);
            acc[3] = ffma2(wb.y, yd, acc[3]);
            ulonglong2 wc = wp[2], wd = wp[3];
            acc[4] = ffma2(wc.x, yd, acc[4]);
            acc[5] = ffma2(wc.y, yd, acc[5]);
            acc[6] = ffma2(wd.x, yd, acc[6]);
            acc[7] = ffma2(wd.y, yd, acc[7]);
        }
#pragma unroll
        for (int m = 0; m < 8; ++m) {
            acc[m] = addf2(acc[m], __shfl_xor_sync(0xffffffffu, acc[m], 1));
            acc[m] = addf2(acc[m], __shfl_xor_sync(0xffffffffu, acc[m], 2));
            acc[m] = addf2(acc[m], __shfl_xor_sync(0xffffffffu, acc[m], 4));
        }
        if (q8 == 0) {
            float2* og = (float2*)(ob + (size_t)((NTILES - 1) * TT + t3) * 16);
#pragma unroll
            for (int m = 0; m < 8; ++m) og[m] = unpack2(acc[m]);
        }
    }
}

extern "C" void kernel_launch(void* const* d_in, const int* in_sizes, int n_in,
                              void* d_out, int out_size)
{
    const float* x  = (const float*)d_in[0];
    const float* W1 = (const float*)d_in[1];
    const float* W2 = (const float*)d_in[2];
    float* out = (float*)d_out;

    // +BPAD slack: P2 prefetch reads one row past the second buffer.
    const size_t smem = (size_t)(256 * WPAD + 2 * TT * XPAD + 2 * TT * BPAD + BPAD) * sizeof(float);
    cudaFuncSetAttribute(fused_fea_kernel, cudaFuncAttributeMaxDynamicSharedMemorySize, (int)smem);
    fused_fea_kernel<<<256, NTHREADS, smem>>>(x, W1, W2, out);
}

// round 6
// speedup vs baseline: 1.2670x; 1.2670x over previous
#include <cuda_runtime.h>

// Warp-specialized pipeline, 256 threads/CTA, 2 CTAs/SM, one CTA per batch.
//   tid 0-127  (G): P1 (fc1, t-packed f32x2) + P3 (fc2, t-tiled register GEMM)
//   tid 128-223(S): 96 sequential material chains, 4-timestep batched LDS/STS
//   tid 224-255:    stages x tiles global->shared (transposed [f][t])
// buf layout: [l][TPAD] (channel-major, time contiguous) — enables LDS.128
// over 4 timesteps in P2/P3 and STS.128 in P1.

typedef unsigned long long u64;

#define NTHREADS 256
#define TT 32
#define NTILES 32
#define TPAD 36            // buf row stride (floats); mult of 4, conflict-checked
#define XPAD 36            // x tile row stride [f][t]
#define WPAD 20            // SW2 row stride [l][o]
#define XSZ  (16 * XPAD)
#define BSZ  (256 * TPAD)

__device__ __forceinline__ u64 ffma2(u64 a, u64 b, u64 c) {
    u64 d; asm("fma.rn.f32x2 %0, %1, %2, %3;" : "=l"(d) : "l"(a), "l"(b), "l"(c)); return d;
}
__device__ __forceinline__ u64 addf2(u64 a, u64 b) {
    u64 d; asm("add.rn.f32x2 %0, %1, %2;" : "=l"(d) : "l"(a), "l"(b)); return d;
}
__device__ __forceinline__ u64 dup2(float a) {
    u64 r; asm("mov.b64 %0, {%1, %1};" : "=l"(r) : "f"(a)); return r;
}
__device__ __forceinline__ float2 unpack2(u64 v) {
    float2 r; asm("mov.b64 {%0, %1}, %2;" : "=f"(r.x), "=f"(r.y) : "l"(v)); return r;
}

// ---- material constants (reference float32 values) ----
#define NUv    0.3f
#define CEL00  (200.0f / 0.91f)
#define CEL01  (CEL00 * 0.3f)
#define CEL22  (CEL00 * 0.35f)
#define INV_E  (1.0f / 200.0f)
#define INV_G  (2.6f / 200.0f)
#define GMODc  (200.0f / 2.6f)
#define SY0c   2.0f
#define HARDc  10.0f
#define INV3GH (1.0f / (3.0f * GMODc + HARDc))
#define KPEN   50.0f
#define D0c    0.1f
#define INV_DFm (1.0f / 0.9f)

// One J2 radial-return step; e* in, stress out via e* refs; state by ref.
__device__ __forceinline__ void j2_step(float& e1, float& e2, float& e12,
                                        float& ep1, float& ep2, float& ep12, float& epbar)
{
    float d1 = e1 - ep1, d2 = e2 - ep2, d12 = e12 - ep12;
    float s1  = CEL00 * d1 + CEL01 * d2;
    float s2  = CEL01 * d1 + CEL00 * d2;
    float s12 = CEL22 * d12;
    float qv  = fmaxf(s1 * s1 - s1 * s2 + s2 * s2 + 3.0f * s12 * s12, 1e-12f);
    float rs  = rsqrtf(qv);
    float seq = qv * rs;
    float fy  = seq - (SY0c + HARDc * epbar);
    bool  pl  = fy > 0.0f;
    epbar += fmaxf(fy, 0.0f) * INV3GH;
    float r = pl ? (SY0c + HARDc * epbar) * rs : 1.0f;
    s1 *= r; s2 *= r; s12 *= r;
    ep1  = pl ? e1  - (s1 - NUv * s2) * INV_E : ep1;
    ep2  = pl ? e2  - (s2 - NUv * s1) * INV_E : ep2;
    ep12 = pl ? e12 - s12 * INV_G             : ep12;
    e1 = s1; e2 = s2; e12 = s12;
}

__device__ __forceinline__ void coh_step(float& dn, float& ds, float& hist)
{
    float dnp = fmaxf(dn, 0.0f);
    float q2  = fmaxf(dnp * dnp + ds * ds, 1e-12f);
    float lam = q2 * rsqrtf(q2);
    hist = fmaxf(hist, lam);
    float dmg = __fdividef(hist - D0c, hist) * INV_DFm;
    dmg = fminf(fmaxf(dmg, 0.0f), 1.0f);
    float omd = 1.0f - dmg;
    float tn = KPEN * dn * (dn > 0.0f ? omd : 1.0f);
    ds = omd * KPEN * ds;
    dn = tn;
}

__global__ void __launch_bounds__(NTHREADS, 2)
fused_fea_kernel(const float* __restrict__ x, const float* __restrict__ W1,
                 const float* __restrict__ W2, float* __restrict__ out)
{
    extern __shared__ float sm[];
    float* SW2s = sm;                    // 256*WPAD
    float* xsd  = sm + 256 * WPAD;       // 2 * XSZ, x transposed [f][t]
    float* buf  = xsd + 2 * XSZ;         // 2 * BSZ, [l][t]

    const int tid = threadIdx.x;
    const int b   = blockIdx.x;
    const bool isG = (tid < 128);

    const float* xb = x   + (size_t)b * (1024 * 16);
    float*       ob = out + (size_t)b * (1024 * 16);

    // ---- Prologue: softplus(W2) staged [l][o]; stager fills x tiles 0,1 ----
    for (int i = tid; i < 4096; i += NTHREADS) {
        int o = i >> 8, l = i & 255;
        SW2s[l * WPAD + o] = log1pf(expf(W2[i]));
    }
    if (tid >= 224) {
        const int j = tid - 224;
#pragma unroll
        for (int tile = 0; tile < 2; ++tile) {
            const float4* src = (const float4*)(xb + tile * (TT * 16) + j * 16);
            float* dst = xsd + tile * XSZ + j;   // column j of [f][t]
            float4 v0 = src[0], v1 = src[1], v2 = src[2], v3 = src[3];
            dst[0*XPAD] = v0.x; dst[1*XPAD]  = v0.y; dst[2*XPAD]  = v0.z; dst[3*XPAD]  = v0.w;
            dst[4*XPAD] = v1.x; dst[5*XPAD]  = v1.y; dst[6*XPAD]  = v1.z; dst[7*XPAD]  = v1.w;
            dst[8*XPAD] = v2.x; dst[9*XPAD]  = v2.y; dst[10*XPAD] = v2.z; dst[11*XPAD] = v2.w;
            dst[12*XPAD]= v3.x; dst[13*XPAD] = v3.y; dst[14*XPAD] = v3.z; dst[15*XPAD] = v3.w;
        }
    }

    // G setup: channels c0 = tid, c1 = tid+128; duplicated weights in regs.
    // Row map: bulk channels (l<192) -> row l; cohesive l>=192 -> comp-planar
    // row = 192 + ((l-192)>>1) + 32*(l&1)  (dn rows 192..223, ds rows 224..255).
    u64 wd0[16], wd1[16];
    int row0 = 0, row1 = 0;
    if (isG) {
        const int c0 = tid, c1 = tid + 128;
        row0 = c0;
        row1 = (c1 < 192) ? c1 : 192 + ((c1 - 192) >> 1) + 32 * (c1 & 1);
#pragma unroll
        for (int f = 0; f < 16; ++f) {
            wd0[f] = dup2(W1[c0 * 16 + f]);
            wd1[f] = dup2(W1[c1 * 16 + f]);
        }
    }

    // S state
    float ep1 = 0.f, ep2 = 0.f, ep12 = 0.f, epbar = 0.f, hist = 0.f;
    const int s = tid - 128;

    // P3 thread coords: lc = l-strip (l = 8i+lc), ob = output half, tb = t-quad.
    const int lc = tid & 7;
    const int obh = (tid >> 3) & 1;
    const int tb  = tid >> 4;            // 0..7 for G threads
    const int rowc_base = 192 + (lc >> 1) + 32 * (lc & 1);  // cohesive row base (i>=24)

    __syncthreads();

    // ================= P1 (one tile) =================
#define P1_TILE(BSEL, XSEL)                                                   \
    {                                                                         \
        float* bufb = buf + (BSEL) * BSZ;                                     \
        const float* xsb = xsd + (XSEL) * XSZ;                                \
        _Pragma("unroll")                                                     \
        for (int g = 0; g < 8; ++g) {                                         \
            const int t = g * 4;                                              \
            u64 a00 = 0, a01 = 0, a10 = 0, a11 = 0;                           \
            _Pragma("unroll")                                                 \
            for (int f = 0; f < 16; ++f) {                                    \
                ulonglong2 xv = *(const ulonglong2*)(xsb + f * XPAD + t);     \
                a00 = ffma2(wd0[f], xv.x, a00);                               \
                a01 = ffma2(wd0[f], xv.y, a01);                               \
                a10 = ffma2(wd1[f], xv.x, a10);                               \
                a11 = ffma2(wd1[f], xv.y, a11);                               \
            }                                                                 \
            ulonglong2 s0; s0.x = a00; s0.y = a01;                            \
            ulonglong2 s1v; s1v.x = a10; s1v.y = a11;                         \
            *(ulonglong2*)(bufb + row0 * TPAD + t) = s0;                      \
            *(ulonglong2*)(bufb + row1 * TPAD + t) = s1v;                     \
        }                                                                     \
    }

    // ================= P3 (one tile) =================
#define P3_TILE(BSEL, TOUT)                                                   \
    {                                                                         \
        const float* bufb = buf + (BSEL) * BSZ;                               \
        u64 acc[16];                                                          \
        _Pragma("unroll")                                                     \
        for (int m = 0; m < 16; ++m) acc[m] = 0ull;                           \
        const float* ybulk = bufb + lc * TPAD + 4 * tb;                       \
        const float* wrow  = SW2s + lc * WPAD + 8 * obh;                      \
        _Pragma("unroll 4")                                                   \
        for (int i = 0; i < 24; ++i) {                                        \
            ulonglong2 yv = *(const ulonglong2*)(ybulk + i * 8 * TPAD);       \
            ulonglong2 wa = *(const ulonglong2*)(wrow + i * 8 * WPAD);        \
            ulonglong2 wb = *(const ulonglong2*)(wrow + i * 8 * WPAD + 4);    \
            float2 y01 = unpack2(yv.x), y23 = unpack2(yv.y);                  \
            u64 y0 = dup2(y01.x), y1 = dup2(y01.y);                           \
            u64 y2 = dup2(y23.x), y3 = dup2(y23.y);                           \
            acc[0]  = ffma2(wa.x, y0, acc[0]);  acc[1]  = ffma2(wa.y, y0, acc[1]);   \
            acc[2]  = ffma2(wb.x, y0, acc[2]);  acc[3]  = ffma2(wb.y, y0, acc[3]);   \
            acc[4]  = ffma2(wa.x, y1, acc[4]);  acc[5]  = ffma2(wa.y, y1, acc[5]);   \
            acc[6]  = ffma2(wb.x, y1, acc[6]);  acc[7]  = ffma2(wb.y, y1, acc[7]);   \
            acc[8]  = ffma2(wa.x, y2, acc[8]);  acc[9]  = ffma2(wa.y, y2, acc[9]);   \
            acc[10] = ffma2(wb.x, y2, acc[10]); acc[11] = ffma2(wb.y, y2, acc[11]);  \
            acc[12] = ffma2(wa.x, y3, acc[12]); acc[13] = ffma2(wa.y, y3, acc[13]);  \
            acc[14] = ffma2(wb.x, y3, acc[14]); acc[15] = ffma2(wb.y, y3, acc[15]);  \
        }                                                                     \
        const float* ycoh = bufb + rowc_base * TPAD + 4 * tb;                 \
        _Pragma("unroll 4")                                                   \
        for (int i = 24; i < 32; ++i) {                                       \
            ulonglong2 yv = *(const ulonglong2*)(ycoh + (i - 24) * 4 * TPAD); \
            ulonglong2 wa = *(const ulonglong2*)(wrow + i * 8 * WPAD);        \
            ulonglong2 wb = *(const ulonglong2*)(wrow + i * 8 * WPAD + 4);    \
            float2 y01 = unpack2(yv.x), y23 = unpack2(yv.y);                  \
            u64 y0 = dup2(y01.x), y1 = dup2(y01.y);                           \
            u64 y2 = dup2(y23.x), y3 = dup2(y23.y);                           \
            acc[0]  = ffma2(wa.x, y0, acc[0]);  acc[1]  = ffma2(wa.y, y0, acc[1]);   \
            acc[2]  = ffma2(wb.x, y0, acc[2]);  acc[3]  = ffma2(wb.y, y0, acc[3]);   \
            acc[4]  = ffma2(wa.x, y1, acc[4]);  acc[5]  = ffma2(wa.y, y1, acc[5]);   \
            acc[6]  = ffma2(wb.x, y1, acc[6]);  acc[7]  = ffma2(wb.y, y1, acc[7]);   \
            acc[8]  = ffma2(wa.x, y2, acc[8]);  acc[9]  = ffma2(wa.y, y2, acc[9]);   \
            acc[10] = ffma2(wb.x, y2, acc[10]); acc[11] = ffma2(wb.y, y2, acc[11]);  \
            acc[12] = ffma2(wa.x, y3, acc[12]); acc[13] = ffma2(wa.y, y3, acc[13]);  \
            acc[14] = ffma2(wb.x, y3, acc[14]); acc[15] = ffma2(wb.y, y3, acc[15]);  \
        }                                                                     \
        _Pragma("unroll")                                                     \
        for (int m = 0; m < 16; ++m) {                                        \
            acc[m] = addf2(acc[m], __shfl_xor_sync(0xffffffffu, acc[m], 1));  \
            acc[m] = addf2(acc[m], __shfl_xor_sync(0xffffffffu, acc[m], 2));  \
            acc[m] = addf2(acc[m], __shfl_xor_sync(0xffffffffu, acc[m], 4));  \
        }                                                                     \
        if (lc == 0) {                                                        \
            float* og = ob + (size_t)((TOUT) + 4 * tb) * 16 + 8 * obh;        \
            _Pragma("unroll")                                                 \
            for (int j = 0; j < 4; ++j) {                                     \
                float2 p0 = unpack2(acc[j * 4 + 0]);                          \
                float2 p1 = unpack2(acc[j * 4 + 1]);                          \
                float2 p2 = unpack2(acc[j * 4 + 2]);                          \
                float2 p3 = unpack2(acc[j * 4 + 3]);                          \
                float4 v0; v0.x = p0.x; v0.y = p0.y; v0.z = p1.x; v0.w = p1.y; \
                float4 v1; v1.x = p2.x; v1.y = p2.y; v1.z = p3.x; v1.w = p3.y; \
                *(float4*)(og + j * 16)     = v0;                             \
                *(float4*)(og + j * 16 + 4) = v1;                             \
            }                                                                 \
        }                                                                     \
    }

    // ---- Fill: P1(0) ----
    if (isG) P1_TILE(0, 0);
    __syncthreads();

    // ---- Pipelined slots ----
    for (int k = 0; k < NTILES; ++k) {
        if (isG) {
            if (k >= 1) P3_TILE((k - 1) & 1, (k - 1) * TT);
            asm volatile("bar.sync 1, 128;" ::: "memory");
            if (k + 1 < NTILES) P1_TILE((k + 1) & 1, (k + 1) & 1);
        } else if (s < 64) {
            // J2 bulk: rows 3s, 3s+1, 3s+2; 4 timesteps per LDS.128/STS.128.
            float* r0 = buf + (k & 1) * BSZ + (3 * s) * TPAD;
#pragma unroll
            for (int g = 0; g < 8; ++g) {
                float4 E1 = *(float4*)(r0 + 4 * g);
                float4 E2 = *(float4*)(r0 + TPAD + 4 * g);
                float4 E3 = *(float4*)(r0 + 2 * TPAD + 4 * g);
                j2_step(E1.x, E2.x, E3.x, ep1, ep2, ep12, epbar);
                j2_step(E1.y, E2.y, E3.y, ep1, ep2, ep12, epbar);
                j2_step(E1.z, E2.z, E3.z, ep1, ep2, ep12, epbar);
                j2_step(E1.w, E2.w, E3.w, ep1, ep2, ep12, epbar);
                *(float4*)(r0 + 4 * g) = E1;
                *(float4*)(r0 + TPAD + 4 * g) = E2;
                *(float4*)(r0 + 2 * TPAD + 4 * g) = E3;
            }
        } else if (s < 96) {
            // Cohesive: dn row 192+j, ds row 224+j.
            const int j = s - 64;
            float* rdn = buf + (k & 1) * BSZ + (192 + j) * TPAD;
            float* rds = buf + (k & 1) * BSZ + (224 + j) * TPAD;
#pragma unroll
            for (int g = 0; g < 8; ++g) {
                float4 DN = *(float4*)(rdn + 4 * g);
                float4 DS = *(float4*)(rds + 4 * g);
                coh_step(DN.x, DS.x, hist);
                coh_step(DN.y, DS.y, hist);
                coh_step(DN.z, DS.z, hist);
                coh_step(DN.w, DS.w, hist);
                *(float4*)(rdn + 4 * g) = DN;
                *(float4*)(rds + 4 * g) = DS;
            }
        } else {
            // Stager: x tile (k+2) -> xsd[k&1], transposed [f][t].
            if (k + 2 < NTILES) {
                const int j = tid - 224;
                const float4* src = (const float4*)(xb + (k + 2) * (TT * 16) + j * 16);
                float* dst = xsd + (k & 1) * XSZ + j;
                float4 v0 = src[0], v1 = src[1], v2 = src[2], v3 = src[3];
                dst[0*XPAD] = v0.x; dst[1*XPAD]  = v0.y; dst[2*XPAD]  = v0.z; dst[3*XPAD]  = v0.w;
                dst[4*XPAD] = v1.x; dst[5*XPAD]  = v1.y; dst[6*XPAD]  = v1.z; dst[7*XPAD]  = v1.w;
                dst[8*XPAD] = v2.x; dst[9*XPAD]  = v2.y; dst[10*XPAD] = v2.z; dst[11*XPAD] = v2.w;
                dst[12*XPAD]= v3.x; dst[13*XPAD] = v3.y; dst[14*XPAD] = v3.z; dst[15*XPAD] = v3.w;
            }
        }
        __syncthreads();
    }

    // ---- Drain: P3(NTILES-1) ----
    if (isG) P3_TILE((NTILES - 1) & 1, (NTILES - 1) * TT);
}

extern "C" void kernel_launch(void* const* d_in, const int* in_sizes, int n_in,
                              void* d_out, int out_size)
{
    const float* x  = (const float*)d_in[0];
    const float* W1 = (const float*)d_in[1];
    const float* W2 = (const float*)d_in[2];
    float* out = (float*)d_out;

    const size_t smem = (size_t)(256 * WPAD + 2 * XSZ + 2 * BSZ) * sizeof(float); // 98816 B
    cudaFuncSetAttribute(fused_fea_kernel, cudaFuncAttributeMaxDynamicSharedMemorySize, (int)smem);
    fused_fea_kernel<<<256, NTHREADS, smem>>>(x, W1, W2, out);
}

// round 7
// speedup vs baseline: 1.3158x; 1.0385x over previous
#include <cuda_runtime.h>

// Warp-specialized pipeline, 384 threads/CTA, 2 CTAs/SM, one CTA per batch.
//   tid 0-255  (G, 8 warps): P1 (fc1) + P3 (fc2), f32x2 packed FMA.
//   tid 256-351(S, 3 warps): 96 sequential material chains, 4-t batched LDS/STS.
//   tid 352-383:             stages x tiles global->shared (transposed [f][t]).
// buf layout [l][TPAD] (time contiguous): LDS.128 covers 4 timesteps.

typedef unsigned long long u64;

#define NTHREADS 384
#define TT 32
#define NTILES 32
#define TPAD 36
#define XPAD 36
#define WPAD 20
#define XSZ  (16 * XPAD)
#define BSZ  (256 * TPAD)

__device__ __forceinline__ u64 ffma2(u64 a, u64 b, u64 c) {
    u64 d; asm("fma.rn.f32x2 %0, %1, %2, %3;" : "=l"(d) : "l"(a), "l"(b), "l"(c)); return d;
}
__device__ __forceinline__ u64 addf2(u64 a, u64 b) {
    u64 d; asm("add.rn.f32x2 %0, %1, %2;" : "=l"(d) : "l"(a), "l"(b)); return d;
}
__device__ __forceinline__ u64 dup2(float a) {
    u64 r; asm("mov.b64 %0, {%1, %1};" : "=l"(r) : "f"(a)); return r;
}
__device__ __forceinline__ float2 unpack2(u64 v) {
    float2 r; asm("mov.b64 {%0, %1}, %2;" : "=f"(r.x), "=f"(r.y) : "l"(v)); return r;
}

// ---- material constants (reference float32 values) ----
#define NUv    0.3f
#define CEL00  (200.0f / 0.91f)
#define CEL01  (CEL00 * 0.3f)
#define CEL22  (CEL00 * 0.35f)
#define INV_E  (1.0f / 200.0f)
#define INV_G  (2.6f / 200.0f)
#define GMODc  (200.0f / 2.6f)
#define SY0c   2.0f
#define HARDc  10.0f
#define INV3GH (1.0f / (3.0f * GMODc + HARDc))
#define KPEN   50.0f
#define D0c    0.1f
#define INV_DFm (1.0f / 0.9f)

__device__ __forceinline__ void j2_step(float& e1, float& e2, float& e12,
                                        float& ep1, float& ep2, float& ep12, float& epbar)
{
    float d1 = e1 - ep1, d2 = e2 - ep2, d12 = e12 - ep12;
    float s1  = CEL00 * d1 + CEL01 * d2;
    float s2  = CEL01 * d1 + CEL00 * d2;
    float s12 = CEL22 * d12;
    float qv  = fmaxf(s1 * s1 - s1 * s2 + s2 * s2 + 3.0f * s12 * s12, 1e-12f);
    float rs  = rsqrtf(qv);
    float seq = qv * rs;
    float fy  = seq - (SY0c + HARDc * epbar);
    bool  pl  = fy > 0.0f;
    epbar += fmaxf(fy, 0.0f) * INV3GH;
    float r = pl ? (SY0c + HARDc * epbar) * rs : 1.0f;
    s1 *= r; s2 *= r; s12 *= r;
    ep1  = pl ? e1  - (s1 - NUv * s2) * INV_E : ep1;
    ep2  = pl ? e2  - (s2 - NUv * s1) * INV_E : ep2;
    ep12 = pl ? e12 - s12 * INV_G             : ep12;
    e1 = s1; e2 = s2; e12 = s12;
}

__device__ __forceinline__ void coh_step(float& dn, float& ds, float& hist)
{
    float dnp = fmaxf(dn, 0.0f);
    float q2  = fmaxf(dnp * dnp + ds * ds, 1e-12f);
    float lam = q2 * rsqrtf(q2);
    hist = fmaxf(hist, lam);
    float dmg = __fdividef(hist - D0c, hist) * INV_DFm;
    dmg = fminf(fmaxf(dmg, 0.0f), 1.0f);
    float omd = 1.0f - dmg;
    float tn = KPEN * dn * (dn > 0.0f ? omd : 1.0f);
    ds = omd * KPEN * ds;
    dn = tn;
}

__global__ void __launch_bounds__(NTHREADS, 2)
fused_fea_kernel(const float* __restrict__ x, const float* __restrict__ W1,
                 const float* __restrict__ W2, float* __restrict__ out)
{
    extern __shared__ float sm[];
    float* SW2s = sm;                    // 256*WPAD
    float* xsd  = sm + 256 * WPAD;       // 2 * XSZ, x transposed [f][t]
    float* buf  = xsd + 2 * XSZ;         // 2 * BSZ, [l][t]

    const int tid = threadIdx.x;
    const int b   = blockIdx.x;
    const bool isG = (tid < 256);

    const float* xb = x   + (size_t)b * (1024 * 16);
    float*       ob = out + (size_t)b * (1024 * 16);

    // ---- Prologue ----
    for (int i = tid; i < 4096; i += NTHREADS) {
        int o = i >> 8, l = i & 255;
        SW2s[l * WPAD + o] = log1pf(expf(W2[i]));
    }
    if (tid >= 352) {
        const int j = tid - 352;
#pragma unroll
        for (int tile = 0; tile < 2; ++tile) {
            const float4* src = (const float4*)(xb + tile * (TT * 16) + j * 16);
            float* dst = xsd + tile * XSZ + j;
            float4 v0 = src[0], v1 = src[1], v2 = src[2], v3 = src[3];
            dst[0*XPAD] = v0.x; dst[1*XPAD]  = v0.y; dst[2*XPAD]  = v0.z; dst[3*XPAD]  = v0.w;
            dst[4*XPAD] = v1.x; dst[5*XPAD]  = v1.y; dst[6*XPAD]  = v1.z; dst[7*XPAD]  = v1.w;
            dst[8*XPAD] = v2.x; dst[9*XPAD]  = v2.y; dst[10*XPAD] = v2.z; dst[11*XPAD] = v2.w;
            dst[12*XPAD]= v3.x; dst[13*XPAD] = v3.y; dst[14*XPAD] = v3.z; dst[15*XPAD] = v3.w;
        }
    }

    // G/P1 setup: one channel per thread (c = tid), duplicated weights in regs.
    // Cohesive channels l>=192 stored comp-planar: row = 192+((l-192)>>1)+32*(l&1).
    u64 wd[16];
    int rowp = 0;
    if (isG) {
        const int c = tid;
        rowp = (c < 192) ? c : 192 + ((c - 192) >> 1) + 32 * (c & 1);
#pragma unroll
        for (int f = 0; f < 16; ++f) wd[f] = dup2(W1[c * 16 + f]);
    }

    // S state
    float ep1 = 0.f, ep2 = 0.f, ep12 = 0.f, epbar = 0.f, hist = 0.f;
    const int s = tid - 256;

    // P3 coords: lc = l-strip (l = 8i+lc), ob2 = output quad, tb = t-quad.
    const int lc  = tid & 7;
    const int ob2 = (tid >> 3) & 3;
    const int tb  = tid >> 5;            // 0..7 for G threads
    const int rowc_base = 192 + (lc >> 1) + 32 * (lc & 1);

    __syncthreads();

    // ================= P1 (one tile) =================
#define P1_TILE(BSEL, XSEL)                                                   \
    {                                                                         \
        float* bufb = buf + (BSEL) * BSZ;                                     \
        const float* xsb = xsd + (XSEL) * XSZ;                                \
        _Pragma("unroll")                                                     \
        for (int g = 0; g < 8; ++g) {                                         \
            const int t = g * 4;                                              \
            u64 a0 = 0, a1 = 0;                                               \
            _Pragma("unroll")                                                 \
            for (int f = 0; f < 16; ++f) {                                    \
                ulonglong2 xv = *(const ulonglong2*)(xsb + f * XPAD + t);     \
                a0 = ffma2(wd[f], xv.x, a0);                                  \
                a1 = ffma2(wd[f], xv.y, a1);                                  \
            }                                                                 \
            ulonglong2 sv; sv.x = a0; sv.y = a1;                              \
            *(ulonglong2*)(bufb + rowp * TPAD + t) = sv;                      \
        }                                                                     \
    }

    // ================= P3 (one tile) =================
#define P3_TILE(BSEL, TOUT)                                                   \
    {                                                                         \
        const float* bufb = buf + (BSEL) * BSZ;                               \
        u64 acc[8];                                                           \
        _Pragma("unroll")                                                     \
        for (int m = 0; m < 8; ++m) acc[m] = 0ull;                            \
        const float* ybulk = bufb + lc * TPAD + 4 * tb;                       \
        const float* wrow  = SW2s + lc * WPAD + 4 * ob2;                      \
        _Pragma("unroll 4")                                                   \
        for (int i = 0; i < 24; ++i) {                                        \
            ulonglong2 yv = *(const ulonglong2*)(ybulk + i * 8 * TPAD);       \
            ulonglong2 wv = *(const ulonglong2*)(wrow + i * 8 * WPAD);        \
            float2 y01 = unpack2(yv.x), y23 = unpack2(yv.y);                  \
            u64 y0 = dup2(y01.x), y1 = dup2(y01.y);                           \
            u64 y2 = dup2(y23.x), y3 = dup2(y23.y);                           \
            acc[0] = ffma2(wv.x, y0, acc[0]); acc[1] = ffma2(wv.y, y0, acc[1]); \
            acc[2] = ffma2(wv.x, y1, acc[2]); acc[3] = ffma2(wv.y, y1, acc[3]); \
            acc[4] = ffma2(wv.x, y2, acc[4]); acc[5] = ffma2(wv.y, y2, acc[5]); \
            acc[6] = ffma2(wv.x, y3, acc[6]); acc[7] = ffma2(wv.y, y3, acc[7]); \
        }                                                                     \
        const float* ycoh = bufb + rowc_base * TPAD + 4 * tb;                 \
        _Pragma("unroll 4")                                                   \
        for (int i = 24; i < 32; ++i) {                                       \
            ulonglong2 yv = *(const ulonglong2*)(ycoh + (i - 24) * 4 * TPAD); \
            ulonglong2 wv = *(const ulonglong2*)(wrow + i * 8 * WPAD);        \
            float2 y01 = unpack2(yv.x), y23 = unpack2(yv.y);                  \
            u64 y0 = dup2(y01.x), y1 = dup2(y01.y);                           \
            u64 y2 = dup2(y23.x), y3 = dup2(y23.y);                           \
            acc[0] = ffma2(wv.x, y0, acc[0]); acc[1] = ffma2(wv.y, y0, acc[1]); \
            acc[2] = ffma2(wv.x, y1, acc[2]); acc[3] = ffma2(wv.y, y1, acc[3]); \
            acc[4] = ffma2(wv.x, y2, acc[4]); acc[5] = ffma2(wv.y, y2, acc[5]); \
            acc[6] = ffma2(wv.x, y3, acc[6]); acc[7] = ffma2(wv.y, y3, acc[7]); \
        }                                                                     \
        _Pragma("unroll")                                                     \
        for (int m = 0; m < 8; ++m) {                                         \
            acc[m] = addf2(acc[m], __shfl_xor_sync(0xffffffffu, acc[m], 1));  \
            acc[m] = addf2(acc[m], __shfl_xor_sync(0xffffffffu, acc[m], 2));  \
            acc[m] = addf2(acc[m], __shfl_xor_sync(0xffffffffu, acc[m], 4));  \
        }                                                                     \
        if (lc == 0) {                                                        \
            float* og = ob + (size_t)((TOUT) + 4 * tb) * 16 + 4 * ob2;        \
            _Pragma("unroll")                                                 \
            for (int j = 0; j < 4; ++j) {                                     \
                float2 p0 = unpack2(acc[2 * j]);                              \
                float2 p1 = unpack2(acc[2 * j + 1]);                          \
                float4 v; v.x = p0.x; v.y = p0.y; v.z = p1.x; v.w = p1.y;     \
                *(float4*)(og + j * 16) = v;                                  \
            }                                                                 \
        }                                                                     \
    }

    // ---- Fill: P1(0) ----
    if (isG) P1_TILE(0, 0);
    __syncthreads();

    // ---- Pipelined slots ----
    for (int k = 0; k < NTILES; ++k) {
        if (isG) {
            if (k >= 1) P3_TILE((k - 1) & 1, (k - 1) * TT);
            asm volatile("bar.sync 1, 256;" ::: "memory");
            if (k + 1 < NTILES) P1_TILE((k + 1) & 1, (k + 1) & 1);
        } else if (s < 64) {
            // J2 bulk: rows 3s..3s+2; 4 timesteps per LDS/STS.128.
            float* r0 = buf + (k & 1) * BSZ + (3 * s) * TPAD;
#pragma unroll
            for (int g = 0; g < 8; ++g) {
                float4 E1 = *(float4*)(r0 + 4 * g);
                float4 E2 = *(float4*)(r0 + TPAD + 4 * g);
                float4 E3 = *(float4*)(r0 + 2 * TPAD + 4 * g);
                j2_step(E1.x, E2.x, E3.x, ep1, ep2, ep12, epbar);
                j2_step(E1.y, E2.y, E3.y, ep1, ep2, ep12, epbar);
                j2_step(E1.z, E2.z, E3.z, ep1, ep2, ep12, epbar);
                j2_step(E1.w, E2.w, E3.w, ep1, ep2, ep12, epbar);
                *(float4*)(r0 + 4 * g) = E1;
                *(float4*)(r0 + TPAD + 4 * g) = E2;
                *(float4*)(r0 + 2 * TPAD + 4 * g) = E3;
            }
        } else if (s < 96) {
            // Cohesive: dn row 192+j, ds row 224+j.
            const int j = s - 64;
            float* rdn = buf + (k & 1) * BSZ + (192 + j) * TPAD;
            float* rds = buf + (k & 1) * BSZ + (224 + j) * TPAD;
#pragma unroll
            for (int g = 0; g < 8; ++g) {
                float4 DN = *(float4*)(rdn + 4 * g);
                float4 DS = *(float4*)(rds + 4 * g);
                coh_step(DN.x, DS.x, hist);
                coh_step(DN.y, DS.y, hist);
                coh_step(DN.z, DS.z, hist);
                coh_step(DN.w, DS.w, hist);
                *(float4*)(rdn + 4 * g) = DN;
                *(float4*)(rds + 4 * g) = DS;
            }
        } else {
            // Stager: x tile (k+2) -> xsd[k&1], transposed [f][t].
            if (k + 2 < NTILES) {
                const int j = tid - 352;
                const float4* src = (const float4*)(xb + (k + 2) * (TT * 16) + j * 16);
                float* dst = xsd + (k & 1) * XSZ + j;
                float4 v0 = src[0], v1 = src[1], v2 = src[2], v3 = src[3];
                dst[0*XPAD] = v0.x; dst[1*XPAD]  = v0.y; dst[2*XPAD]  = v0.z; dst[3*XPAD]  = v0.w;
                dst[4*XPAD] = v1.x; dst[5*XPAD]  = v1.y; dst[6*XPAD]  = v1.z; dst[7*XPAD]  = v1.w;
                dst[8*XPAD] = v2.x; dst[9*XPAD]  = v2.y; dst[10*XPAD] = v2.z; dst[11*XPAD] = v2.w;
                dst[12*XPAD]= v3.x; dst[13*XPAD] = v3.y; dst[14*XPAD] = v3.z; dst[15*XPAD] = v3.w;
            }
        }
        __syncthreads();
    }

    // ---- Drain: P3(NTILES-1) ----
    if (isG) P3_TILE((NTILES - 1) & 1, (NTILES - 1) * TT);
}

extern "C" void kernel_launch(void* const* d_in, const int* in_sizes, int n_in,
                              void* d_out, int out_size)
{
    const float* x  = (const float*)d_in[0];
    const float* W1 = (const float*)d_in[1];
    const float* W2 = (const float*)d_in[2];
    float* out = (float*)d_out;

    const size_t smem = (size_t)(256 * WPAD + 2 * XSZ + 2 * BSZ) * sizeof(float); // 98816 B
    cudaFuncSetAttribute(fused_fea_kernel, cudaFuncAttributeMaxDynamicSharedMemorySize, (int)smem);
    fused_fea_kernel<<<256, NTHREADS, smem>>>(x, W1, W2, out);
}